// round 17
// baseline (speedup 1.0000x reference)
#include <cuda_runtime.h>

#define BATCH 8
#define DIM 256
#define SEQ 16384
#define KK 3
#define HID 85
#define OUTC (DIM*KK)
#define BN_EPS 1e-5f
#define FULLM 0xffffffffu

// Scratch (device globals — no allocation allowed). g_cnt self-resets.
__device__ float g_pooled[BATCH * DIM];
__device__ float g_y[BATCH * HID];
__device__ unsigned g_cnt[BATCH];

// ---------------------------------------------------------------------------
// Kernel 1: pool (R3-exact hot loop) + per-batch y[85] finisher tail.
// grid=(DIM, BATCH), block=512. Last block of batch b (atomic counter)
// computes y = ReLU(BN(w1 @ pooled[b])) with 4 threads per hidden unit
// (~2us, overlapped with other batches' pool blocks).
// ---------------------------------------------------------------------------
__global__ void pool_y_kernel(const float* __restrict__ x,
                              const float* __restrict__ w1,
                              const float* __restrict__ gamma,
                              const float* __restrict__ beta,
                              const float* __restrict__ mean,
                              const float* __restrict__ var) {
    const int c = blockIdx.x;
    const int b = blockIdx.y;
    const int tid = threadIdx.x;
    const int bid = b * DIM + c;
    const size_t rowoff = (size_t)bid * SEQ;
    const float4* row = (const float4*)(x + rowoff);

    float4 v[8];
    #pragma unroll
    for (int j = 0; j < 8; j++)
        v[j] = row[tid + j * 512];

    float s = 0.f;
    #pragma unroll
    for (int j = 0; j < 8; j++)
        s += (v[j].x + v[j].y) + (v[j].z + v[j].w);

    #pragma unroll
    for (int off = 16; off > 0; off >>= 1)
        s += __shfl_down_sync(FULLM, s, off);

    __shared__ float sm[16];
    __shared__ int sh_last;
    if ((tid & 31) == 0) sm[tid >> 5] = s;
    __syncthreads();
    if (tid < 16) {
        float t = sm[tid];
        #pragma unroll
        for (int off = 8; off > 0; off >>= 1)
            t += __shfl_down_sync(0xffffu, t, off);
        if (tid == 0) {
            g_pooled[bid] = t * (1.f / SEQ);
            __threadfence();                          // release pooled row
            unsigned r = atomicAdd(&g_cnt[b], 1u);
            sh_last = (r == DIM - 1);
        }
    }
    __syncthreads();
    if (!sh_last) return;

    // ---- finisher: y[85] for batch b ----
    __threadfence();                                  // acquire pooled[b]
    __shared__ float ps[DIM];
    if (tid < DIM) ps[tid] = __ldcg(g_pooled + b * DIM + tid);
    __syncthreads();

    if (tid < HID * 4) {                              // 340 threads, 4 per h
        const int h = tid >> 2;
        const int q = tid & 3;
        const float* wr = w1 + h * DIM + q * 64;
        const float* pp = ps + q * 64;
        float acc = 0.f;
        #pragma unroll 8
        for (int k = 0; k < 64; k++) acc = fmaf(__ldg(wr + k), pp[k], acc);
        acc += __shfl_down_sync(FULLM, acc, 2);
        acc += __shfl_down_sync(FULLM, acc, 1);
        if (q == 0) {
            float y = (acc - mean[h]) * (gamma[h] * rsqrtf(var[h] + BN_EPS)) + beta[h];
            g_y[b * HID + h] = fmaxf(y, 0.f);
        }
    }
    if (tid == 0) g_cnt[b] = 0;                       // reset for next replay
}

// ---------------------------------------------------------------------------
// Kernel 2: depthwise conv (R3-exact hot loop) + per-CTA w-tap head.
// grid=(8, DIM, BATCH), block=256, 2 float4/thread, halo via shuffle,
// reversed traversal, __stcs stores. Threads 0-2 compute the 3 taps from
// g_y + w2 (85 MACs each; w2 row ~1KB, L2-resident after first CTA of the
// row) WHILE the x loads are in flight.
// ---------------------------------------------------------------------------
__global__ void conv_kernel(const float* __restrict__ x,
                            const float* __restrict__ w2,
                            const float* __restrict__ b2,
                            const float* __restrict__ bias,
                            float* __restrict__ out) {
    const int b = (BATCH - 1) - blockIdx.z;
    const int c = (DIM - 1) - blockIdx.y;
    const int chunk = (int)(gridDim.x - 1) - blockIdx.x;     // 0..7
    const int tid = threadIdx.x;
    const int lane = tid & 31;
    const size_t rowoff = ((size_t)b * DIM + c) * SEQ;

    const int p0 = chunk * 256 + tid;          // float4 idx, first half
    const int p1 = p0 + 2048;                  // second half
    const int t0 = p0 * 4;
    const int t1 = p1 * 4;

    // ---- issue the big x loads first ----
    const float4 xa = *(const float4*)(x + rowoff + t0);
    const float4 xb = *(const float4*)(x + rowoff + t1);

    // ---- head: taps from y while loads fly ----
    __shared__ float wsh[4];
    if (tid < KK) {
        const int o = c * KK + tid;
        const float* wr = w2 + o * HID;
        const float* yy = g_y + b * HID;
        float acc = __ldg(b2 + o);
        #pragma unroll 5
        for (int h = 0; h < HID; h++) acc = fmaf(__ldg(wr + h), __ldcg(yy + h), acc);
        wsh[tid] = acc;
    }
    if (tid == KK) wsh[KK] = __ldg(bias + c);

    float xla = __shfl_up_sync(FULLM, xa.w, 1);
    float xra = __shfl_down_sync(FULLM, xa.x, 1);
    float xlb = __shfl_up_sync(FULLM, xb.w, 1);
    float xrb = __shfl_down_sync(FULLM, xb.x, 1);

    if (lane == 0) {
        xla = (t0 == 0) ? 0.f : __ldg(x + rowoff + t0 - 1);
        xlb = __ldg(x + rowoff + t1 - 1);
    }
    if (lane == 31) {
        xra = __ldg(x + rowoff + t0 + 4);
        xrb = (t1 + 4 >= SEQ) ? 0.f : __ldg(x + rowoff + t1 + 4);
    }

    __syncthreads();
    const float w0  = wsh[0];
    const float w1v = wsh[1];
    const float w2v = wsh[2];
    const float bb  = wsh[3];

    float4 oa, ob;
    oa.x = fmaf(w0, xla,  fmaf(w1v, xa.x, fmaf(w2v, xa.y, bb)));
    oa.y = fmaf(w0, xa.x, fmaf(w1v, xa.y, fmaf(w2v, xa.z, bb)));
    oa.z = fmaf(w0, xa.y, fmaf(w1v, xa.z, fmaf(w2v, xa.w, bb)));
    oa.w = fmaf(w0, xa.z, fmaf(w1v, xa.w, fmaf(w2v, xra,  bb)));

    ob.x = fmaf(w0, xlb,  fmaf(w1v, xb.x, fmaf(w2v, xb.y, bb)));
    ob.y = fmaf(w0, xb.x, fmaf(w1v, xb.y, fmaf(w2v, xb.z, bb)));
    ob.z = fmaf(w0, xb.y, fmaf(w1v, xb.z, fmaf(w2v, xb.w, bb)));
    ob.w = fmaf(w0, xb.z, fmaf(w1v, xb.w, fmaf(w2v, xrb,  bb)));

    __stcs((float4*)(out + rowoff + t0), oa);
    __stcs((float4*)(out + rowoff + t1), ob);
}

// ---------------------------------------------------------------------------
// Launch. Inputs (metadata order): x, w1, bn_gamma, bn_beta, bn_mean, bn_var,
// w2, b2, bias. Output: fp32 [8, 256, 16384].
// ---------------------------------------------------------------------------
extern "C" void kernel_launch(void* const* d_in, const int* in_sizes, int n_in,
                              void* d_out, int out_size) {
    const float* x     = (const float*)d_in[0];
    const float* w1    = (const float*)d_in[1];
    const float* gamma = (const float*)d_in[2];
    const float* beta  = (const float*)d_in[3];
    const float* mean  = (const float*)d_in[4];
    const float* var   = (const float*)d_in[5];
    const float* w2    = (const float*)d_in[6];
    const float* b2    = (const float*)d_in[7];
    const float* bias  = (const float*)d_in[8];
    float* out = (float*)d_out;

    dim3 pg(DIM, BATCH);
    pool_y_kernel<<<pg, 512>>>(x, w1, gamma, beta, mean, var);

    dim3 cg(8, DIM, BATCH);
    conv_kernel<<<cg, 256>>>(x, w2, b2, bias, out);
}